// round 3
// baseline (speedup 1.0000x reference)
#include <cuda_runtime.h>
#include <math.h>

#define NS 1024
#define NR 4096
#define TPB 256
#define RPT (NR / TPB)              // residues per thread = 16
#define TILE_WORDS (NR * 3)         // 12288 floats
#define TILE_BYTES (TILE_WORDS * 4) // 49152 bytes
#define STAGE_F4 (TILE_WORDS / 4 / TPB) // 12 float4 per thread

// ---------------- scratch (static device globals; no allocation) ----------------
__device__ __align__(16) float4 g_wt4[NR];  // (w*t_c0, w*t_c1, w*t_c2, w)
__device__ float g_stats[8];                // [4]=1/Lt, [5]=1/d0^2

__device__ __forceinline__ float warpsum(float v) {
#pragma unroll
    for (int o = 16; o; o >>= 1) v += __shfl_down_sync(0xffffffffu, v, o);
    return v;
}

__device__ __forceinline__ float rcp_fast(float x) {
    float r;
    asm("rcp.approx.f32 %0, %1;" : "=f"(r) : "f"(x));
    return r;
}

// ---------------- kernel A: true-structure statistics + companion array ----------------
__global__ void k_pre(const float* __restrict__ truec, const int* __restrict__ mask) {
    int tid = threadIdx.x;
    float ws = 0.f, wt0 = 0.f, wt1 = 0.f, wt2 = 0.f;
    for (int l = tid; l < NR; l += TPB) {
        float w = (mask[l] != 0) ? 1.0f : 0.0f;
        float t0 = truec[l * 3 + 0];
        float t1 = truec[l * 3 + 1];
        float t2 = truec[l * 3 + 2];
        ws += w; wt0 += w * t0; wt1 += w * t1; wt2 += w * t2;
    }
    __shared__ float sm[4][8];
    __shared__ float s_tm[3];
    int lane = tid & 31, wid = tid >> 5;
    ws = warpsum(ws); wt0 = warpsum(wt0); wt1 = warpsum(wt1); wt2 = warpsum(wt2);
    if (lane == 0) { sm[0][wid] = ws; sm[1][wid] = wt0; sm[2][wid] = wt1; sm[3][wid] = wt2; }
    __syncthreads();
    if (tid == 0) {
        float Lt = 0.f, a = 0.f, b = 0.f, c = 0.f;
        for (int i = 0; i < 8; i++) { Lt += sm[0][i]; a += sm[1][i]; b += sm[2][i]; c += sm[3][i]; }
        float inv = 1.0f / Lt;
        float m0 = a * inv, m1 = b * inv, m2 = c * inv;
        float d0 = (Lt <= 15.0f) ? 0.5f : (1.24f * cbrtf(Lt - 15.0f) - 1.8f);
        d0 = fmaxf(d0, 0.5f);
        g_stats[0] = m0; g_stats[1] = m1; g_stats[2] = m2;
        g_stats[3] = Lt; g_stats[4] = inv; g_stats[5] = 1.0f / (d0 * d0);
        s_tm[0] = m0; s_tm[1] = m1; s_tm[2] = m2;
    }
    __syncthreads();
    float m0 = s_tm[0], m1 = s_tm[1], m2 = s_tm[2];
    for (int l = tid; l < NR; l += TPB) {
        float w = (mask[l] != 0) ? 1.0f : 0.0f;
        float4 v;
        v.x = w * (truec[l * 3 + 0] - m0);
        v.y = w * (truec[l * 3 + 1] - m1);
        v.z = w * (truec[l * 3 + 2] - m2);
        v.w = w;
        g_wt4[l] = v;
    }
}

// ---------------- fused kernel: stage -> cov -> rotation -> TM ----------------
extern __shared__ float s_tile[];   // TILE_WORDS floats (one full sample)

__global__ void __launch_bounds__(TPB, 4) k_fused(const float* __restrict__ pred,
                                                  float* __restrict__ out) {
    int s = blockIdx.x;
    int tid = threadIdx.x;
    int lane = tid & 31, wid = tid >> 5;

    __shared__ float red[12][8];
    __shared__ float bc[16];    // R(9), c(3), invd0, invLt

    // ---- stage: coalesced float4 copy gmem -> smem ----
    {
        const float4* __restrict__ p4 =
            reinterpret_cast<const float4*>(pred + (size_t)s * TILE_WORDS);
        float4* st4 = reinterpret_cast<float4*>(s_tile);
        float4 tmp[STAGE_F4];
#pragma unroll
        for (int k = 0; k < STAGE_F4; k++) tmp[k] = p4[tid + k * TPB];
#pragma unroll
        for (int k = 0; k < STAGE_F4; k++) st4[tid + k * TPB] = tmp[k];
    }
    __syncthreads();

    // ---- pass 1: covariance S = sum p * (w t_c)^T and P = sum w p ----
    float S00 = 0, S01 = 0, S02 = 0, S10 = 0, S11 = 0, S12 = 0, S20 = 0, S21 = 0, S22 = 0;
    float P0 = 0, P1 = 0, P2 = 0;
#pragma unroll
    for (int k = 0; k < RPT; k++) {
        int l = tid + k * TPB;
        float px = s_tile[3 * l + 0];
        float py = s_tile[3 * l + 1];
        float pz = s_tile[3 * l + 2];
        float4 wt = g_wt4[l];
        S00 = fmaf(px, wt.x, S00); S01 = fmaf(px, wt.y, S01); S02 = fmaf(px, wt.z, S02);
        S10 = fmaf(py, wt.x, S10); S11 = fmaf(py, wt.y, S11); S12 = fmaf(py, wt.z, S12);
        S20 = fmaf(pz, wt.x, S20); S21 = fmaf(pz, wt.y, S21); S22 = fmaf(pz, wt.z, S22);
        P0 = fmaf(wt.w, px, P0); P1 = fmaf(wt.w, py, P1); P2 = fmaf(wt.w, pz, P2);
    }
    {
        float vals[12] = {S00, S01, S02, S10, S11, S12, S20, S21, S22, P0, P1, P2};
#pragma unroll
        for (int k = 0; k < 12; k++) {
            float v = warpsum(vals[k]);
            if (lane == 0) red[k][wid] = v;
        }
    }
    __syncthreads();

    // ---- rotation (thread 0): Horn quaternion via 4x4 Jacobi ----
    if (tid == 0) {
        float Sf[12];
#pragma unroll
        for (int i = 0; i < 12; i++) {
            float v = 0.f;
#pragma unroll
            for (int j = 0; j < 8; j++) v += red[i][j];
            Sf[i] = v;
        }
        float Sxx = Sf[0], Sxy = Sf[1], Sxz = Sf[2];
        float Syx = Sf[3], Syy = Sf[4], Syz = Sf[5];
        float Szx = Sf[6], Szy = Sf[7], Szz = Sf[8];

        float A[4][4];
        A[0][0] = Sxx + Syy + Szz; A[0][1] = Syz - Szy;         A[0][2] = Szx - Sxz;         A[0][3] = Sxy - Syx;
        A[1][1] = Sxx - Syy - Szz; A[1][2] = Sxy + Syx;         A[1][3] = Szx + Sxz;
        A[2][2] = -Sxx + Syy - Szz; A[2][3] = Syz + Szy;
        A[3][3] = -Sxx - Syy + Szz;
        A[1][0] = A[0][1]; A[2][0] = A[0][2]; A[3][0] = A[0][3];
        A[2][1] = A[1][2]; A[3][1] = A[1][3]; A[3][2] = A[2][3];

        float V[4][4] = {{1, 0, 0, 0}, {0, 1, 0, 0}, {0, 0, 1, 0}, {0, 0, 0, 1}};

        for (int sweep = 0; sweep < 6; sweep++) {
#pragma unroll
            for (int p = 0; p < 3; p++) {
#pragma unroll
                for (int q = p + 1; q < 4; q++) {
                    float apq = A[p][q];
                    float scale = fabsf(A[p][p]) + fabsf(A[q][q]);
                    if (fabsf(apq) > 1e-12f * scale + 1e-30f) {
                        float theta = (A[q][q] - A[p][p]) / (2.0f * apq);
                        float t = 1.0f / (fabsf(theta) + sqrtf(theta * theta + 1.0f));
                        if (theta < 0.0f) t = -t;
                        float cth = 1.0f / sqrtf(t * t + 1.0f);
                        float sth = t * cth;
#pragma unroll
                        for (int r = 0; r < 4; r++) {
                            float arp = A[r][p], arq = A[r][q];
                            A[r][p] = arp * cth - arq * sth;
                            A[r][q] = arp * sth + arq * cth;
                        }
#pragma unroll
                        for (int r = 0; r < 4; r++) {
                            float apr = A[p][r], aqr = A[q][r];
                            A[p][r] = apr * cth - aqr * sth;
                            A[q][r] = apr * sth + aqr * cth;
                        }
#pragma unroll
                        for (int r = 0; r < 4; r++) {
                            float vrp = V[r][p], vrq = V[r][q];
                            V[r][p] = vrp * cth - vrq * sth;
                            V[r][q] = vrp * sth + vrq * cth;
                        }
                    }
                }
            }
        }

        int kk = 0;
        float best = A[0][0];
#pragma unroll
        for (int i = 1; i < 4; i++) if (A[i][i] > best) { best = A[i][i]; kk = i; }
        float q0 = V[0][kk], qx = V[1][kk], qy = V[2][kk], qz = V[3][kk];

        float R[3][3];
        R[0][0] = q0 * q0 + qx * qx - qy * qy - qz * qz;
        R[0][1] = 2.0f * (qx * qy - q0 * qz);
        R[0][2] = 2.0f * (qx * qz + q0 * qy);
        R[1][0] = 2.0f * (qy * qx + q0 * qz);
        R[1][1] = q0 * q0 - qx * qx + qy * qy - qz * qz;
        R[1][2] = 2.0f * (qy * qz - q0 * qx);
        R[2][0] = 2.0f * (qz * qx - q0 * qy);
        R[2][1] = 2.0f * (qz * qy + q0 * qx);
        R[2][2] = q0 * q0 - qx * qx - qy * qy + qz * qz;

        // orientation safeguard: objective = sum_ij R_ij S_ji; transpose if better
        float Sm[3][3] = {{Sxx, Sxy, Sxz}, {Syx, Syy, Syz}, {Szx, Szy, Szz}};
        float obj = 0.f, objT = 0.f;
#pragma unroll
        for (int i = 0; i < 3; i++)
#pragma unroll
            for (int j = 0; j < 3; j++) {
                obj  += R[i][j] * Sm[j][i];
                objT += R[j][i] * Sm[j][i];
            }
        if (objT > obj) {
#pragma unroll
            for (int i = 0; i < 3; i++)
#pragma unroll
                for (int j = i + 1; j < 3; j++) {
                    float tmp = R[i][j]; R[i][j] = R[j][i]; R[j][i] = tmp;
                }
        }

        float invLt = g_stats[4];
        float pm0 = Sf[9] * invLt, pm1 = Sf[10] * invLt, pm2 = Sf[11] * invLt;
        bc[0] = R[0][0]; bc[1] = R[0][1]; bc[2] = R[0][2];
        bc[3] = R[1][0]; bc[4] = R[1][1]; bc[5] = R[1][2];
        bc[6] = R[2][0]; bc[7] = R[2][1]; bc[8] = R[2][2];
        bc[9]  = R[0][0] * pm0 + R[0][1] * pm1 + R[0][2] * pm2;
        bc[10] = R[1][0] * pm0 + R[1][1] * pm1 + R[1][2] * pm2;
        bc[11] = R[2][0] * pm0 + R[2][1] * pm1 + R[2][2] * pm2;
        bc[12] = g_stats[5];   // 1/d0^2
        bc[13] = invLt;
    }
    __syncthreads();

    // ---- pass 2: TM score from smem tile ----
    float R00 = bc[0], R01 = bc[1], R02 = bc[2];
    float R10 = bc[3], R11 = bc[4], R12 = bc[5];
    float R20 = bc[6], R21 = bc[7], R22 = bc[8];
    float c0 = bc[9], c1 = bc[10], c2 = bc[11];
    float invd0 = bc[12], invLt = bc[13];

    float acc = 0.f;
#pragma unroll
    for (int k = 0; k < RPT; k++) {
        int l = tid + k * TPB;
        float px = s_tile[3 * l + 0];
        float py = s_tile[3 * l + 1];
        float pz = s_tile[3 * l + 2];
        float4 wt = g_wt4[l];
        // wt.xyz == t_c when w==1; when w==0 the term is multiplied by wt.w==0 anyway
        float dx = fmaf(R00, px, fmaf(R01, py, fmaf(R02, pz, -c0))) - wt.x;
        float dy = fmaf(R10, px, fmaf(R11, py, fmaf(R12, pz, -c1))) - wt.y;
        float dz = fmaf(R20, px, fmaf(R21, py, fmaf(R22, pz, -c2))) - wt.z;
        float dsq = fmaf(dx, dx, fmaf(dy, dy, dz * dz));
        acc += wt.w * rcp_fast(fmaf(dsq, invd0, 1.0f));
    }

    acc = warpsum(acc);
    if (lane == 0) red[0][wid] = acc;
    __syncthreads();
    if (tid == 0) {
        float v = 0.f;
#pragma unroll
        for (int i = 0; i < 8; i++) v += red[0][i];
        out[s] = v * invLt;
    }
}

// ---------------- launch ----------------
extern "C" void kernel_launch(void* const* d_in, const int* in_sizes, int n_in,
                              void* d_out, int out_size) {
    const float* pred = (const float*)d_in[0];
    const float* truec = (const float*)d_in[1];
    const int* mask = (const int*)d_in[2];
    float* out = (float*)d_out;

    cudaFuncSetAttribute(k_fused, cudaFuncAttributeMaxDynamicSharedMemorySize, TILE_BYTES);

    k_pre<<<1, TPB>>>(truec, mask);
    k_fused<<<NS, TPB, TILE_BYTES>>>(pred, out);
}